// round 2
// baseline (speedup 1.0000x reference)
#include <cuda_runtime.h>
#include <math.h>

// Problem dims
#define BB 32     // batch
#define TT 256    // listener time steps
#define DD 512    // listener feature dim (= H)
#define HH 512    // hidden
#define VV 2000   // vocab
#define MM 256    // attention MLP dim
#define KX 2512   // V + H  (LSTM0 input dim)
#define NSTEP 100

// ---------------- device scratch (no allocation allowed) ----------------
__device__ float g_X0[KX * BB];        // x_t transposed: [k][b]; rows [0,2000)=raw_pred, [2000,2512)=context
__device__ float g_h0a[HH * BB], g_h0b[HH * BB];
__device__ float g_h1a[HH * BB], g_h1b[HH * BB];
__device__ float g_c0[HH * BB], g_c1[HH * BB];
__device__ float g_ctx[DD * BB];       // context transposed [d][b]
__device__ float g_logits[VV * BB];    // [v][b]
__device__ float g_complis[BB * MM * TT];   // relu(psi(listener)) as [b][m][t]
__device__ float g_WphiT[HH * MM];     // [d][m]
__device__ float g_WpsiT[DD * MM];     // [d][m]

// ---------------- block reductions (256 threads, 8 warps) ----------------
__device__ __forceinline__ float blockMax256(float v, float* red) {
    #pragma unroll
    for (int o = 16; o; o >>= 1) v = fmaxf(v, __shfl_xor_sync(0xffffffffu, v, o));
    int w = threadIdx.x >> 5;
    if ((threadIdx.x & 31) == 0) red[w] = v;
    __syncthreads();
    float r = red[0];
    #pragma unroll
    for (int i = 1; i < 8; i++) r = fmaxf(r, red[i]);
    __syncthreads();
    return r;
}

__device__ __forceinline__ float blockSum256(float v, float* red) {
    #pragma unroll
    for (int o = 16; o; o >>= 1) v += __shfl_xor_sync(0xffffffffu, v, o);
    int w = threadIdx.x >> 5;
    if ((threadIdx.x & 31) == 0) red[w] = v;
    __syncthreads();
    float r = red[0];
    #pragma unroll
    for (int i = 1; i < 8; i++) r += red[i];
    __syncthreads();
    return r;
}

// ---------------- init: x0, states, weight transposes ----------------
__global__ void init_kernel(const float* __restrict__ Lf,
                            const float* __restrict__ Wphi,
                            const float* __restrict__ Wpsi) {
    const int S_X0  = KX * BB;                 // 80384
    const int S_Z   = S_X0 + 4 * HH * BB;      // + h0a,h1a,c0,c1 zeros -> 145920
    const int S_PHI = S_Z + HH * MM;           // +131072 -> 276992
    const int S_PSI = S_PHI + DD * MM;         // +131072 -> 408064
    for (int i = blockIdx.x * blockDim.x + threadIdx.x; i < S_PSI;
         i += gridDim.x * blockDim.x) {
        if (i < S_X0) {
            int r = i / BB, b = i % BB;
            float v;
            if (r < VV) v = (r == 0) ? 1.0f : 0.0f;
            else        v = Lf[b * TT * DD + (r - VV)];   // listener[b,0,d]
            g_X0[i] = v;
        } else if (i < S_Z) {
            int j = i - S_X0;
            int seg = j / (HH * BB), k = j % (HH * BB);
            if      (seg == 0) g_h0a[k] = 0.f;
            else if (seg == 1) g_h1a[k] = 0.f;
            else if (seg == 2) g_c0[k]  = 0.f;
            else               g_c1[k]  = 0.f;
        } else if (i < S_PHI) {
            int j = i - S_Z;
            int d = j / MM, m = j % MM;
            g_WphiT[j] = Wphi[m * HH + d];
        } else {
            int j = i - S_PHI;
            int d = j / MM, m = j % MM;
            g_WpsiT[j] = Wpsi[m * DD + d];
        }
    }
}

// ---------------- psi precompute: comp_lis[b][m][t] ----------------
// grid: 32 b * 16 t-tiles = 512 blocks, 256 threads (thread = m), 16 t per block
__global__ void psi_kernel(const float* __restrict__ Lf, const float* __restrict__ bpsi) {
    __shared__ float Ls[16][512];
    int b  = blockIdx.x >> 4;
    int t0 = (blockIdx.x & 15) * 16;
    int m  = threadIdx.x;
    for (int i = threadIdx.x; i < 16 * 512; i += 256) {
        int r = i >> 9, c = i & 511;
        Ls[r][c] = Lf[b * TT * DD + (t0 + r) * DD + c];
    }
    __syncthreads();
    float acc[16];
    float bp = bpsi[m];
    #pragma unroll
    for (int j = 0; j < 16; j++) acc[j] = bp;
    for (int d = 0; d < 512; d += 4) {
        float w0 = g_WpsiT[(d + 0) * MM + m];
        float w1 = g_WpsiT[(d + 1) * MM + m];
        float w2 = g_WpsiT[(d + 2) * MM + m];
        float w3 = g_WpsiT[(d + 3) * MM + m];
        #pragma unroll
        for (int j = 0; j < 16; j++) {
            float4 lv = *(const float4*)&Ls[j][d];
            acc[j] = fmaf(w0, lv.x, acc[j]);
            acc[j] = fmaf(w1, lv.y, acc[j]);
            acc[j] = fmaf(w2, lv.z, acc[j]);
            acc[j] = fmaf(w3, lv.w, acc[j]);
        }
    }
    float* dst = &g_complis[b * MM * TT + m * TT + t0];
    #pragma unroll
    for (int j = 0; j < 16; j++) dst[j] = fmaxf(acc[j], 0.f);
}

// ---------------- LSTM cell: warp per hidden unit u, lane = batch ----------------
// gates = Wih @ x + Whh @ h + biases ; torch order i,f,g,o in row blocks of HH
template <int KIN>
__global__ void lstm_kernel(const float* __restrict__ Wih, const float* __restrict__ Whh,
                            const float* __restrict__ bih, const float* __restrict__ bhh,
                            const float* __restrict__ xin,   // [KIN][32]
                            const float* __restrict__ hprev, // [HH][32]
                            float* __restrict__ hnew,        // [HH][32]
                            float* __restrict__ cst) {       // [HH][32]
    int u = (blockIdx.x * blockDim.x + threadIdx.x) >> 5;
    int lane = threadIdx.x & 31;
    if (u >= HH) return;
    const float* wi = Wih + (size_t)u * KIN;
    const float* wf = Wih + (size_t)(HH + u) * KIN;
    const float* wg = Wih + (size_t)(2 * HH + u) * KIN;
    const float* wo = Wih + (size_t)(3 * HH + u) * KIN;
    float ai = 0.f, af = 0.f, ag = 0.f, ao = 0.f;
    for (int k = 0; k < KIN; k += 4) {
        float x0 = xin[(k + 0) * 32 + lane];
        float x1 = xin[(k + 1) * 32 + lane];
        float x2 = xin[(k + 2) * 32 + lane];
        float x3 = xin[(k + 3) * 32 + lane];
        float4 a = *(const float4*)(wi + k);
        float4 b = *(const float4*)(wf + k);
        float4 c = *(const float4*)(wg + k);
        float4 d = *(const float4*)(wo + k);
        ai = fmaf(a.x, x0, ai); ai = fmaf(a.y, x1, ai); ai = fmaf(a.z, x2, ai); ai = fmaf(a.w, x3, ai);
        af = fmaf(b.x, x0, af); af = fmaf(b.y, x1, af); af = fmaf(b.z, x2, af); af = fmaf(b.w, x3, af);
        ag = fmaf(c.x, x0, ag); ag = fmaf(c.y, x1, ag); ag = fmaf(c.z, x2, ag); ag = fmaf(c.w, x3, ag);
        ao = fmaf(d.x, x0, ao); ao = fmaf(d.y, x1, ao); ao = fmaf(d.z, x2, ao); ao = fmaf(d.w, x3, ao);
    }
    const float* vi = Whh + (size_t)u * HH;
    const float* vf = Whh + (size_t)(HH + u) * HH;
    const float* vg = Whh + (size_t)(2 * HH + u) * HH;
    const float* vo = Whh + (size_t)(3 * HH + u) * HH;
    for (int k = 0; k < HH; k += 4) {
        float x0 = hprev[(k + 0) * 32 + lane];
        float x1 = hprev[(k + 1) * 32 + lane];
        float x2 = hprev[(k + 2) * 32 + lane];
        float x3 = hprev[(k + 3) * 32 + lane];
        float4 a = *(const float4*)(vi + k);
        float4 b = *(const float4*)(vf + k);
        float4 c = *(const float4*)(vg + k);
        float4 d = *(const float4*)(vo + k);
        ai = fmaf(a.x, x0, ai); ai = fmaf(a.y, x1, ai); ai = fmaf(a.z, x2, ai); ai = fmaf(a.w, x3, ai);
        af = fmaf(b.x, x0, af); af = fmaf(b.y, x1, af); af = fmaf(b.z, x2, af); af = fmaf(b.w, x3, af);
        ag = fmaf(c.x, x0, ag); ag = fmaf(c.y, x1, ag); ag = fmaf(c.z, x2, ag); ag = fmaf(c.w, x3, ag);
        ao = fmaf(d.x, x0, ao); ao = fmaf(d.y, x1, ao); ao = fmaf(d.z, x2, ao); ao = fmaf(d.w, x3, ao);
    }
    float gi = ai + bih[u]          + bhh[u];
    float gf = af + bih[HH + u]     + bhh[HH + u];
    float gg = ag + bih[2 * HH + u] + bhh[2 * HH + u];
    float go = ao + bih[3 * HH + u] + bhh[3 * HH + u];
    float i_ = 1.f / (1.f + expf(-gi));
    float f_ = 1.f / (1.f + expf(-gf));
    float o_ = 1.f / (1.f + expf(-go));
    float t_ = tanhf(gg);
    float cn = f_ * cst[u * 32 + lane] + i_ * t_;
    float hn = o_ * tanhf(cn);
    cst[u * 32 + lane]  = cn;
    hnew[u * 32 + lane] = hn;
}

// ---------------- fused attention: phi -> energy -> softmax -> context ----------------
// block per batch b, 256 threads
__global__ void attn_kernel(const float* __restrict__ Lf,
                            const float* __restrict__ h1,   // [HH][32]
                            const float* __restrict__ bphi,
                            float* __restrict__ attn_out) { // [b][t] for this step
    __shared__ float h1s[512];
    __shared__ float cds[256];
    __shared__ float ats[256];
    __shared__ float red[8];
    int b = blockIdx.x, tid = threadIdx.x;
    h1s[tid]       = h1[tid * 32 + b];
    h1s[tid + 256] = h1[(tid + 256) * 32 + b];
    __syncthreads();
    // phi: comp_dec[m] = relu(Wphi[m,:] . h1 + bphi[m]),  thread = m
    float acc = bphi[tid];
    for (int d = 0; d < 512; d += 4) {
        acc = fmaf(g_WphiT[(d + 0) * MM + tid], h1s[d + 0], acc);
        acc = fmaf(g_WphiT[(d + 1) * MM + tid], h1s[d + 1], acc);
        acc = fmaf(g_WphiT[(d + 2) * MM + tid], h1s[d + 2], acc);
        acc = fmaf(g_WphiT[(d + 3) * MM + tid], h1s[d + 3], acc);
    }
    cds[tid] = fmaxf(acc, 0.f);
    __syncthreads();
    // energy: thread = t
    float e = 0.f;
    const float* cl = &g_complis[b * MM * TT + tid];
    #pragma unroll 4
    for (int m = 0; m < MM; m++) e = fmaf(cds[m], cl[m * TT], e);
    // softmax over t
    float mx = blockMax256(e, red);
    float p = expf(e - mx);
    float s = blockSum256(p, red);
    float a = p / s;
    ats[tid] = a;
    attn_out[b * TT + tid] = a;
    __syncthreads();
    // context: d = tid, tid+256
    #pragma unroll
    for (int dd = 0; dd < 2; dd++) {
        int d = tid + dd * 256;
        float c = 0.f;
        const float* lp = Lf + b * TT * DD + d;
        #pragma unroll 4
        for (int t = 0; t < TT; t++) c = fmaf(ats[t], lp[t * DD], c);
        g_ctx[d * 32 + b]        = c;
        g_X0[(VV + d) * 32 + b]  = c;   // feedback: x_new[2000+d]
    }
}

// ---------------- logits GEMM: warp per vocab row ----------------
__global__ void logits_kernel(const float* __restrict__ Wc, const float* __restrict__ bc,
                              const float* __restrict__ h1) {
    int v = (blockIdx.x * blockDim.x + threadIdx.x) >> 5;
    int lane = threadIdx.x & 31;
    if (v >= VV) return;
    const float* wr = Wc + (size_t)v * 1024;
    float a0 = 0.f, a1 = 0.f, a2 = 0.f, a3 = 0.f;
    for (int k = 0; k < 512; k += 4) {
        float4 w = *(const float4*)(wr + k);
        a0 = fmaf(w.x, h1[(k + 0) * 32 + lane], a0);
        a1 = fmaf(w.y, h1[(k + 1) * 32 + lane], a1);
        a2 = fmaf(w.z, h1[(k + 2) * 32 + lane], a2);
        a3 = fmaf(w.w, h1[(k + 3) * 32 + lane], a3);
    }
    const float* wr2 = wr + 512;
    for (int k = 0; k < 512; k += 4) {
        float4 w = *(const float4*)(wr2 + k);
        a0 = fmaf(w.x, g_ctx[(k + 0) * 32 + lane], a0);
        a1 = fmaf(w.y, g_ctx[(k + 1) * 32 + lane], a1);
        a2 = fmaf(w.z, g_ctx[(k + 2) * 32 + lane], a2);
        a3 = fmaf(w.w, g_ctx[(k + 3) * 32 + lane], a3);
    }
    g_logits[v * 32 + lane] = (a0 + a1) + (a2 + a3) + bc[v];
}

// ---------------- log_softmax + feedback write ----------------
__global__ void lsm_kernel(float* __restrict__ pred_out) {   // [b][v] for this step
    __shared__ float red[8];
    int b = blockIdx.x, tid = threadIdx.x;
    float l[8];
    float mx = -INFINITY;
    #pragma unroll
    for (int j = 0; j < 8; j++) {
        int v = tid + j * 256;
        l[j] = (v < VV) ? g_logits[v * 32 + b] : -INFINITY;
        mx = fmaxf(mx, l[j]);
    }
    mx = blockMax256(mx, red);
    float s = 0.f;
    #pragma unroll
    for (int j = 0; j < 8; j++) s += expf(l[j] - mx);
    s = blockSum256(s, red);
    float lg = logf(s) + mx;
    #pragma unroll
    for (int j = 0; j < 8; j++) {
        int v = tid + j * 256;
        if (v < VV) {
            float lp = l[j] - lg;
            pred_out[b * VV + v] = lp;
            g_X0[v * 32 + b] = lp;   // feedback: x_new[0..1999]
        }
    }
}

// ---------------- host ----------------
extern "C" void kernel_launch(void* const* d_in, const int* in_sizes, int n_in,
                              void* d_out, int out_size) {
    const float* Lf   = (const float*)d_in[0];
    const float* Wih0 = (const float*)d_in[1];
    const float* Whh0 = (const float*)d_in[2];
    const float* bih0 = (const float*)d_in[3];
    const float* bhh0 = (const float*)d_in[4];
    const float* Wih1 = (const float*)d_in[5];
    const float* Whh1 = (const float*)d_in[6];
    const float* bih1 = (const float*)d_in[7];
    const float* bhh1 = (const float*)d_in[8];
    const float* Wphi = (const float*)d_in[9];
    const float* bphi = (const float*)d_in[10];
    const float* Wpsi = (const float*)d_in[11];
    const float* bpsi = (const float*)d_in[12];
    const float* Wc   = (const float*)d_in[13];
    const float* bc   = (const float*)d_in[14];

    float* out = (float*)d_out;
    float* pred_out = out;                                  // [100][32][2000]
    float* attn_out = out + (size_t)NSTEP * BB * VV;        // [100][32][256]

    float *pX0, *ph0a, *ph0b, *ph1a, *ph1b, *pc0, *pc1;
    cudaGetSymbolAddress((void**)&pX0, g_X0);
    cudaGetSymbolAddress((void**)&ph0a, g_h0a);
    cudaGetSymbolAddress((void**)&ph0b, g_h0b);
    cudaGetSymbolAddress((void**)&ph1a, g_h1a);
    cudaGetSymbolAddress((void**)&ph1b, g_h1b);
    cudaGetSymbolAddress((void**)&pc0, g_c0);
    cudaGetSymbolAddress((void**)&pc1, g_c1);

    const int initN = KX * BB + 4 * HH * BB + HH * MM + DD * MM;
    init_kernel<<<(initN + 255) / 256, 256>>>(Lf, Wphi, Wpsi);
    psi_kernel<<<512, 256>>>(Lf, bpsi);

    float *h0p = ph0a, *h0n = ph0b, *h1p = ph1a, *h1n = ph1b;
    for (int t = 0; t < NSTEP; t++) {
        lstm_kernel<KX><<<128, 128>>>(Wih0, Whh0, bih0, bhh0, pX0, h0p, h0n, pc0);
        lstm_kernel<HH><<<128, 128>>>(Wih1, Whh1, bih1, bhh1, h0n, h1p, h1n, pc1);
        attn_kernel<<<32, 256>>>(Lf, h1n, bphi, attn_out + (size_t)t * BB * TT);
        logits_kernel<<<500, 128>>>(Wc, bc, h1n);
        lsm_kernel<<<32, 256>>>(pred_out + (size_t)t * BB * VV);
        float* tmp;
        tmp = h0p; h0p = h0n; h0n = tmp;
        tmp = h1p; h1p = h1n; h1n = tmp;
    }
}

// round 7
// speedup vs baseline: 2.6554x; 2.6554x over previous
#include <cuda_runtime.h>
#include <math.h>

// Problem dims
#define BB 32     // batch
#define TT 256    // listener time steps
#define DD 512    // listener feature dim (= H)
#define HH 512    // hidden
#define VV 2000   // vocab
#define MM 256    // attention MLP dim
#define KX 2512   // V + H  (LSTM0 input dim)
#define NSTEP 100

#define KS0 6     // K-splits LSTM0 (3024/6 = 504 = 126 float4)
#define KC40 126
#define KS1 4     // K-splits LSTM1 (1024/4 = 256 = 64 float4)
#define KC41 64

// Interleaved activation layout: X[k][b] stored at (k/4)*128 + b*4 + (k%4)
__device__ __forceinline__ int XI(int k, int b) { return ((k >> 2) << 7) + (b << 2) + (k & 3); }

// ---------------- device scratch ----------------
__device__ float g_X0[KX * BB];            // interleaved: rows [0,2000)=raw_pred, [2000,2512)=context
__device__ float g_h0i[HH * BB];           // interleaved
__device__ float g_h1i[HH * BB];           // interleaved
__device__ float g_c0[HH * BB], g_c1[HH * BB];   // plain [u][b]
__device__ float g_ctxi[DD * BB];          // interleaved
__device__ float g_gpart[KS0 * 4 * HH * BB];     // gate partials [ks][2048][32]
__device__ float g_lpart[2 * VV * BB];     // logits partials [ks][2000][32]
__device__ float g_complis[BB * MM * TT];  // relu(psi(listener)) as [b][m][t]
__device__ float g_WphiT[HH * MM];         // [d][m]
__device__ float g_WpsiT[DD * MM];         // [d][m]

// ---------------- block reductions (256 threads, 8 warps) ----------------
__device__ __forceinline__ float blockMax256(float v, float* red) {
    #pragma unroll
    for (int o = 16; o; o >>= 1) v = fmaxf(v, __shfl_xor_sync(0xffffffffu, v, o));
    int w = threadIdx.x >> 5;
    if ((threadIdx.x & 31) == 0) red[w] = v;
    __syncthreads();
    float r = red[0];
    #pragma unroll
    for (int i = 1; i < 8; i++) r = fmaxf(r, red[i]);
    __syncthreads();
    return r;
}

__device__ __forceinline__ float blockSum256(float v, float* red) {
    #pragma unroll
    for (int o = 16; o; o >>= 1) v += __shfl_xor_sync(0xffffffffu, v, o);
    int w = threadIdx.x >> 5;
    if ((threadIdx.x & 31) == 0) red[w] = v;
    __syncthreads();
    float r = red[0];
    #pragma unroll
    for (int i = 1; i < 8; i++) r += red[i];
    __syncthreads();
    return r;
}

// ---------------- init: x0 (interleaved), states, weight transposes ----------------
__global__ void init_kernel(const float* __restrict__ Lf,
                            const float* __restrict__ Wphi,
                            const float* __restrict__ Wpsi) {
    const int S_X0  = KX * BB;
    const int S_Z   = S_X0 + 4 * HH * BB;
    const int S_PHI = S_Z + HH * MM;
    const int S_PSI = S_PHI + DD * MM;
    for (int i = blockIdx.x * blockDim.x + threadIdx.x; i < S_PSI;
         i += gridDim.x * blockDim.x) {
        if (i < S_X0) {
            int r = i / BB, b = i % BB;
            float v;
            if (r < VV) v = (r == 0) ? 1.0f : 0.0f;
            else        v = Lf[b * TT * DD + (r - VV)];   // listener[b,0,d]
            g_X0[XI(r, b)] = v;
        } else if (i < S_Z) {
            int j = i - S_X0;
            int seg = j / (HH * BB), k = j % (HH * BB);
            if      (seg == 0) g_h0i[k] = 0.f;
            else if (seg == 1) g_h1i[k] = 0.f;
            else if (seg == 2) g_c0[k]  = 0.f;
            else               g_c1[k]  = 0.f;
        } else if (i < S_PHI) {
            int j = i - S_Z;
            int d = j / MM, m = j % MM;
            g_WphiT[j] = Wphi[m * HH + d];
        } else {
            int j = i - S_PHI;
            int d = j / MM, m = j % MM;
            g_WpsiT[j] = Wpsi[m * DD + d];
        }
    }
}

// ---------------- psi precompute: comp_lis[b][m][t] ----------------
__global__ void psi_kernel(const float* __restrict__ Lf, const float* __restrict__ bpsi) {
    __shared__ float Ls[16][512];
    int b  = blockIdx.x >> 4;
    int t0 = (blockIdx.x & 15) * 16;
    int m  = threadIdx.x;
    for (int i = threadIdx.x; i < 16 * 512; i += 256) {
        int r = i >> 9, c = i & 511;
        Ls[r][c] = Lf[b * TT * DD + (t0 + r) * DD + c];
    }
    __syncthreads();
    float acc[16];
    float bp = bpsi[m];
    #pragma unroll
    for (int j = 0; j < 16; j++) acc[j] = bp;
    for (int d = 0; d < 512; d += 4) {
        float w0 = g_WpsiT[(d + 0) * MM + m];
        float w1 = g_WpsiT[(d + 1) * MM + m];
        float w2 = g_WpsiT[(d + 2) * MM + m];
        float w3 = g_WpsiT[(d + 3) * MM + m];
        #pragma unroll
        for (int j = 0; j < 16; j++) {
            float4 lv = *(const float4*)&Ls[j][d];
            acc[j] = fmaf(w0, lv.x, acc[j]);
            acc[j] = fmaf(w1, lv.y, acc[j]);
            acc[j] = fmaf(w2, lv.z, acc[j]);
            acc[j] = fmaf(w3, lv.w, acc[j]);
        }
    }
    float* dst = &g_complis[b * MM * TT + m * TT + t0];
    #pragma unroll
    for (int j = 0; j < 16; j++) dst[j] = fmaxf(acc[j], 0.f);
}

// ---------------- LSTM gates GEMM (split-K): warp = 4 rows, lane = batch ----------------
// gates[r][b] partial over K-chunk ks. K = XLEN (from Xi) then HH (from Hi).
__global__ void lstm_gemm(const float* __restrict__ Wih, const float* __restrict__ Whh,
                          const float* __restrict__ Xi,  const float* __restrict__ Hi,
                          float* __restrict__ gpart, int XLEN4, int KC4) {
    int w = threadIdx.x >> 5, lane = threadIdx.x & 31;
    int r0 = blockIdx.x * 32 + w * 4;
    int ks = blockIdx.y;
    int s4 = ks * KC4, e4 = s4 + KC4;

    float a0 = 0.f, a1 = 0.f, a2 = 0.f, a3 = 0.f;

    // X segment: k4 in [s4, min(e4, XLEN4))
    int xe4 = (e4 < XLEN4) ? e4 : XLEN4;
    if (s4 < xe4) {
        const float4* xp = (const float4*)Xi + (size_t)s4 * 32 + lane;
        const float4* wp = (const float4*)Wih + (size_t)r0 * XLEN4 + s4;
        #pragma unroll 4
        for (int k4 = s4; k4 < xe4; k4++) {
            float4 x = *xp; xp += 32;
            float4 q0 = wp[0];
            float4 q1 = wp[XLEN4];
            float4 q2 = wp[2 * XLEN4];
            float4 q3 = wp[3 * XLEN4];
            wp++;
            a0 = fmaf(q0.x, x.x, a0); a0 = fmaf(q0.y, x.y, a0); a0 = fmaf(q0.z, x.z, a0); a0 = fmaf(q0.w, x.w, a0);
            a1 = fmaf(q1.x, x.x, a1); a1 = fmaf(q1.y, x.y, a1); a1 = fmaf(q1.z, x.z, a1); a1 = fmaf(q1.w, x.w, a1);
            a2 = fmaf(q2.x, x.x, a2); a2 = fmaf(q2.y, x.y, a2); a2 = fmaf(q2.z, x.z, a2); a2 = fmaf(q2.w, x.w, a2);
            a3 = fmaf(q3.x, x.x, a3); a3 = fmaf(q3.y, x.y, a3); a3 = fmaf(q3.z, x.z, a3); a3 = fmaf(q3.w, x.w, a3);
        }
    }

    // H segment: k4 in [max(s4, XLEN4), e4)
    int hs4 = (s4 > XLEN4) ? s4 : XLEN4;
    if (hs4 < e4) {
        const float4* hp = (const float4*)Hi + (size_t)(hs4 - XLEN4) * 32 + lane;
        const float4* vp = (const float4*)Whh + (size_t)r0 * 128 + (hs4 - XLEN4);
        #pragma unroll 4
        for (int k4 = hs4; k4 < e4; k4++) {
            float4 x = *hp; hp += 32;
            float4 q0 = vp[0];
            float4 q1 = vp[128];
            float4 q2 = vp[256];
            float4 q3 = vp[384];
            vp++;
            a0 = fmaf(q0.x, x.x, a0); a0 = fmaf(q0.y, x.y, a0); a0 = fmaf(q0.z, x.z, a0); a0 = fmaf(q0.w, x.w, a0);
            a1 = fmaf(q1.x, x.x, a1); a1 = fmaf(q1.y, x.y, a1); a1 = fmaf(q1.z, x.z, a1); a1 = fmaf(q1.w, x.w, a1);
            a2 = fmaf(q2.x, x.x, a2); a2 = fmaf(q2.y, x.y, a2); a2 = fmaf(q2.z, x.z, a2); a2 = fmaf(q2.w, x.w, a2);
            a3 = fmaf(q3.x, x.x, a3); a3 = fmaf(q3.y, x.y, a3); a3 = fmaf(q3.z, x.z, a3); a3 = fmaf(q3.w, x.w, a3);
        }
    }

    float* gp = gpart + ((size_t)ks * 2048 + r0) * 32 + lane;
    gp[0]  = a0;
    gp[32] = a1;
    gp[64] = a2;
    gp[96] = a3;
}

// ---------------- LSTM cell: reduce K-splits + nonlinearity ----------------
__global__ void lstm_cell(const float* __restrict__ gpart,
                          const float* __restrict__ bih, const float* __restrict__ bhh,
                          float* __restrict__ hi, float* __restrict__ c, int nks) {
    int idx = blockIdx.x * blockDim.x + threadIdx.x;   // 16384 threads
    int u = idx >> 5, b = idx & 31;
    float g[4];
    #pragma unroll
    for (int gi = 0; gi < 4; gi++) {
        int row = gi * HH + u;
        float s = bih[row] + bhh[row];
        for (int ks = 0; ks < nks; ks++)
            s += gpart[((size_t)ks * 2048 + row) * 32 + b];
        g[gi] = s;
    }
    float i_ = 1.f / (1.f + expf(-g[0]));
    float f_ = 1.f / (1.f + expf(-g[1]));
    float t_ = tanhf(g[2]);
    float o_ = 1.f / (1.f + expf(-g[3]));
    float cn = f_ * c[u * 32 + b] + i_ * t_;
    c[u * 32 + b] = cn;
    hi[XI(u, b)] = o_ * tanhf(cn);
}

// ---------------- fused attention: phi -> energy -> softmax -> context ----------------
__global__ void attn_kernel(const float* __restrict__ Lf,
                            const float* __restrict__ bphi,
                            float* __restrict__ attn_out) { // [b][t] for this step
    __shared__ float h1s[512];
    __shared__ float cds[256];
    __shared__ float ats[256];
    __shared__ float red[8];
    int b = blockIdx.x, tid = threadIdx.x;
    h1s[tid]       = g_h1i[XI(tid, b)];
    h1s[tid + 256] = g_h1i[XI(tid + 256, b)];
    __syncthreads();
    // phi: comp_dec[m] = relu(Wphi[m,:] . h1 + bphi[m]),  thread = m
    float acc = bphi[tid];
    for (int d = 0; d < 512; d += 4) {
        acc = fmaf(g_WphiT[(d + 0) * MM + tid], h1s[d + 0], acc);
        acc = fmaf(g_WphiT[(d + 1) * MM + tid], h1s[d + 1], acc);
        acc = fmaf(g_WphiT[(d + 2) * MM + tid], h1s[d + 2], acc);
        acc = fmaf(g_WphiT[(d + 3) * MM + tid], h1s[d + 3], acc);
    }
    cds[tid] = fmaxf(acc, 0.f);
    __syncthreads();
    // energy: thread = t
    float e = 0.f;
    const float* cl = &g_complis[b * MM * TT + tid];
    #pragma unroll 4
    for (int m = 0; m < MM; m++) e = fmaf(cds[m], cl[m * TT], e);
    // softmax over t
    float mx = blockMax256(e, red);
    float p = expf(e - mx);
    float s = blockSum256(p, red);
    float a = p / s;
    ats[tid] = a;
    attn_out[b * TT + tid] = a;
    __syncthreads();
    // context: d = tid, tid+256
    #pragma unroll
    for (int dd = 0; dd < 2; dd++) {
        int d = tid + dd * 256;
        float cv = 0.f;
        const float* lp = Lf + b * TT * DD + d;
        #pragma unroll 4
        for (int t = 0; t < TT; t++) cv = fmaf(ats[t], lp[t * DD], cv);
        g_ctxi[XI(d, b)]      = cv;
        g_X0[XI(VV + d, b)]   = cv;   // feedback: x_new[2000+d]
    }
}

// ---------------- logits GEMM (split-K=2): warp = 4 vocab rows ----------------
__global__ void logits_gemm(const float* __restrict__ Wc) {
    int w = threadIdx.x >> 5, lane = threadIdx.x & 31;
    int r0 = blockIdx.x * 32 + w * 4;
    if (r0 >= VV) return;
    int ks = blockIdx.y;   // 0: h1 half, 1: ctx half
    const float* src = ks ? g_ctxi : g_h1i;
    const float4* xp = (const float4*)src + lane;
    const float4* wp = (const float4*)Wc + (size_t)r0 * 256 + ks * 128;
    float a0 = 0.f, a1 = 0.f, a2 = 0.f, a3 = 0.f;
    #pragma unroll 4
    for (int k4 = 0; k4 < 128; k4++) {
        float4 x = *xp; xp += 32;
        float4 q0 = wp[0];
        float4 q1 = wp[256];
        float4 q2 = wp[512];
        float4 q3 = wp[768];
        wp++;
        a0 = fmaf(q0.x, x.x, a0); a0 = fmaf(q0.y, x.y, a0); a0 = fmaf(q0.z, x.z, a0); a0 = fmaf(q0.w, x.w, a0);
        a1 = fmaf(q1.x, x.x, a1); a1 = fmaf(q1.y, x.y, a1); a1 = fmaf(q1.z, x.z, a1); a1 = fmaf(q1.w, x.w, a1);
        a2 = fmaf(q2.x, x.x, a2); a2 = fmaf(q2.y, x.y, a2); a2 = fmaf(q2.z, x.z, a2); a2 = fmaf(q2.w, x.w, a2);
        a3 = fmaf(q3.x, x.x, a3); a3 = fmaf(q3.y, x.y, a3); a3 = fmaf(q3.z, x.z, a3); a3 = fmaf(q3.w, x.w, a3);
    }
    float* lp = g_lpart + ((size_t)ks * VV + r0) * 32 + lane;
    lp[0]  = a0;
    lp[32] = a1;
    lp[64] = a2;
    lp[96] = a3;
}

// ---------------- log_softmax + feedback write ----------------
__global__ void lsm_kernel(const float* __restrict__ bc,
                           float* __restrict__ pred_out) {   // [b][v] for this step
    __shared__ float red[8];
    int b = blockIdx.x, tid = threadIdx.x;
    float l[8];
    float mx = -INFINITY;
    #pragma unroll
    for (int j = 0; j < 8; j++) {
        int v = tid + j * 256;
        if (v < VV) {
            l[j] = g_lpart[(size_t)v * 32 + b] + g_lpart[((size_t)VV + v) * 32 + b] + bc[v];
        } else l[j] = -INFINITY;
        mx = fmaxf(mx, l[j]);
    }
    mx = blockMax256(mx, red);
    float s = 0.f;
    #pragma unroll
    for (int j = 0; j < 8; j++) s += expf(l[j] - mx);
    s = blockSum256(s, red);
    float lg = logf(s) + mx;
    #pragma unroll
    for (int j = 0; j < 8; j++) {
        int v = tid + j * 256;
        if (v < VV) {
            float lp = l[j] - lg;
            pred_out[b * VV + v] = lp;
            g_X0[XI(v, b)] = lp;   // feedback: x_new[0..1999]
        }
    }
}

// ---------------- host ----------------
extern "C" void kernel_launch(void* const* d_in, const int* in_sizes, int n_in,
                              void* d_out, int out_size) {
    const float* Lf   = (const float*)d_in[0];
    const float* Wih0 = (const float*)d_in[1];
    const float* Whh0 = (const float*)d_in[2];
    const float* bih0 = (const float*)d_in[3];
    const float* bhh0 = (const float*)d_in[4];
    const float* Wih1 = (const float*)d_in[5];
    const float* Whh1 = (const float*)d_in[6];
    const float* bih1 = (const float*)d_in[7];
    const float* bhh1 = (const float*)d_in[8];
    const float* Wphi = (const float*)d_in[9];
    const float* bphi = (const float*)d_in[10];
    const float* Wpsi = (const float*)d_in[11];
    const float* bpsi = (const float*)d_in[12];
    const float* Wc   = (const float*)d_in[13];
    const float* bc   = (const float*)d_in[14];

    float* out = (float*)d_out;
    float* pred_out = out;                                  // [100][32][2000]
    float* attn_out = out + (size_t)NSTEP * BB * VV;        // [100][32][256]

    float *pX0, *ph0i, *ph1i, *pc0, *pc1, *pgp;
    cudaGetSymbolAddress((void**)&pX0,  g_X0);
    cudaGetSymbolAddress((void**)&ph0i, g_h0i);
    cudaGetSymbolAddress((void**)&ph1i, g_h1i);
    cudaGetSymbolAddress((void**)&pc0,  g_c0);
    cudaGetSymbolAddress((void**)&pc1,  g_c1);
    cudaGetSymbolAddress((void**)&pgp,  g_gpart);

    const int initN = KX * BB + 4 * HH * BB + HH * MM + DD * MM;
    init_kernel<<<(initN + 255) / 256, 256>>>(Lf, Wphi, Wpsi);
    psi_kernel<<<512, 256>>>(Lf, bpsi);

    for (int t = 0; t < NSTEP; t++) {
        lstm_gemm<<<dim3(64, KS0), 256>>>(Wih0, Whh0, pX0, ph0i, pgp, KX / 4, KC40);
        lstm_cell<<<64, 256>>>(pgp, bih0, bhh0, ph0i, pc0, KS0);
        lstm_gemm<<<dim3(64, KS1), 256>>>(Wih1, Whh1, ph0i, ph1i, pgp, HH / 4, KC41);
        lstm_cell<<<64, 256>>>(pgp, bih1, bhh1, ph1i, pc1, KS1);
        attn_kernel<<<32, 256>>>(Lf, bphi, attn_out + (size_t)t * BB * TT);
        logits_gemm<<<dim3(63, 2), 256>>>(Wc);
        lsm_kernel<<<32, 256>>>(bc, pred_out + (size_t)t * BB * VV);
    }
}

// round 8
// speedup vs baseline: 3.7098x; 1.3971x over previous
#include <cuda_runtime.h>
#include <math.h>

// Problem dims
#define BB 32     // batch
#define TT 256    // listener time steps
#define DD 512    // listener feature dim (= H)
#define HH 512    // hidden
#define VV 2000   // vocab
#define MM 256    // attention MLP dim
#define KX 2512   // V + H  (LSTM0 input dim)
#define NSTEP 100

#define NBLK 148
#define NTHR 512
#define NWARP (NBLK * (NTHR / 32))   // 2368 warps

// Interleaved activation layout: X[k][b] stored at (k/4)*128 + b*4 + (k%4)
__device__ __forceinline__ int XI(int k, int b) { return ((k >> 2) << 7) + (b << 2) + (k & 3); }

// ---------------- device scratch ----------------
__device__ float g_X0[KX * BB];            // interleaved: rows [0,2000)=raw_pred, [2000,2512)=context
__device__ float g_h0i[HH * BB];           // interleaved
__device__ float g_h1i[HH * BB];           // interleaved
__device__ float g_c0[HH * BB], g_c1[HH * BB];   // plain [u][b]
__device__ float g_ctxi[DD * BB];          // interleaved
__device__ float g_gpart[4 * 4 * HH * BB]; // gate partials [4][2048][32]
__device__ float g_lpart[4 * VV * BB];     // logits partials [4][2000][32]
__device__ float g_complis[BB * MM * TT];  // relu(psi(listener)) as [b][m][t]
__device__ float g_WphiT[HH * MM];         // [d][m]
__device__ float g_WpsiT[DD * MM];         // [d][m]

// ---------------- software grid barrier (sense-reversing, CG-style) ----------------
__device__ unsigned g_count = 0;
__device__ volatile unsigned g_gen = 0;

__device__ __forceinline__ void gsync() {
    __syncthreads();
    if (threadIdx.x == 0) {
        __threadfence();
        unsigned gen = g_gen;
        if (atomicAdd(&g_count, 1u) == NBLK - 1u) {
            g_count = 0;
            __threadfence();
            g_gen = gen + 1u;
        } else {
            while (g_gen == gen) { }
            __threadfence();
        }
    }
    __syncthreads();
}

// ---------------- block reductions over 512 threads (16 warps) ----------------
__device__ __forceinline__ float bmax512(float v, float* red) {
    #pragma unroll
    for (int o = 16; o; o >>= 1) v = fmaxf(v, __shfl_xor_sync(0xffffffffu, v, o));
    if ((threadIdx.x & 31) == 0) red[threadIdx.x >> 5] = v;
    __syncthreads();
    float r = red[0];
    #pragma unroll
    for (int i = 1; i < 16; i++) r = fmaxf(r, red[i]);
    __syncthreads();
    return r;
}

__device__ __forceinline__ float bsum512(float v, float* red) {
    #pragma unroll
    for (int o = 16; o; o >>= 1) v += __shfl_xor_sync(0xffffffffu, v, o);
    if ((threadIdx.x & 31) == 0) red[threadIdx.x >> 5] = v;
    __syncthreads();
    float r = red[0];
    #pragma unroll
    for (int i = 1; i < 16; i++) r += red[i];
    __syncthreads();
    return r;
}

// ---------------- init: x0 (interleaved), states, weight transposes ----------------
__global__ void init_kernel(const float* __restrict__ Lf,
                            const float* __restrict__ Wphi,
                            const float* __restrict__ Wpsi) {
    const int S_X0  = KX * BB;
    const int S_Z   = S_X0 + 4 * HH * BB;
    const int S_PHI = S_Z + HH * MM;
    const int S_PSI = S_PHI + DD * MM;
    for (int i = blockIdx.x * blockDim.x + threadIdx.x; i < S_PSI;
         i += gridDim.x * blockDim.x) {
        if (i < S_X0) {
            int r = i / BB, b = i % BB;
            float v;
            if (r < VV) v = (r == 0) ? 1.0f : 0.0f;
            else        v = Lf[b * TT * DD + (r - VV)];   // listener[b,0,d]
            g_X0[XI(r, b)] = v;
        } else if (i < S_Z) {
            int j = i - S_X0;
            int seg = j / (HH * BB), k = j % (HH * BB);
            if      (seg == 0) g_h0i[k] = 0.f;
            else if (seg == 1) g_h1i[k] = 0.f;
            else if (seg == 2) g_c0[k]  = 0.f;
            else               g_c1[k]  = 0.f;
        } else if (i < S_PHI) {
            int j = i - S_Z;
            int d = j / MM, m = j % MM;
            g_WphiT[j] = Wphi[m * HH + d];
        } else {
            int j = i - S_PHI;
            int d = j / MM, m = j % MM;
            g_WpsiT[j] = Wpsi[m * DD + d];
        }
    }
}

// ---------------- psi precompute: comp_lis[b][m][t] ----------------
__global__ void psi_kernel(const float* __restrict__ Lf, const float* __restrict__ bpsi) {
    __shared__ float Ls[16][512];
    int b  = blockIdx.x >> 4;
    int t0 = (blockIdx.x & 15) * 16;
    int m  = threadIdx.x;
    for (int i = threadIdx.x; i < 16 * 512; i += 256) {
        int r = i >> 9, c = i & 511;
        Ls[r][c] = Lf[b * TT * DD + (t0 + r) * DD + c];
    }
    __syncthreads();
    float acc[16];
    float bp = bpsi[m];
    #pragma unroll
    for (int j = 0; j < 16; j++) acc[j] = bp;
    for (int d = 0; d < 512; d += 4) {
        float w0 = g_WpsiT[(d + 0) * MM + m];
        float w1 = g_WpsiT[(d + 1) * MM + m];
        float w2 = g_WpsiT[(d + 2) * MM + m];
        float w3 = g_WpsiT[(d + 3) * MM + m];
        #pragma unroll
        for (int j = 0; j < 16; j++) {
            float4 lv = *(const float4*)&Ls[j][d];
            acc[j] = fmaf(w0, lv.x, acc[j]);
            acc[j] = fmaf(w1, lv.y, acc[j]);
            acc[j] = fmaf(w2, lv.z, acc[j]);
            acc[j] = fmaf(w3, lv.w, acc[j]);
        }
    }
    float* dst = &g_complis[b * MM * TT + m * TT + t0];
    #pragma unroll
    for (int j = 0; j < 16; j++) dst[j] = fmaxf(acc[j], 0.f);
}

// ---------------- LSTM gates GEMM phase (split-K=4, 512 row-groups) ----------------
// task = wid*NBLK + blockIdx.x (even spread); ks = task>>9, rg = task&511
__device__ __forceinline__ void gemm_phase(const float* __restrict__ Wih,
                                           const float* __restrict__ Whh,
                                           const float* __restrict__ Xi,
                                           const float* __restrict__ Hi,
                                           int XLEN4, int KC4, int lane) {
    int task0 = (threadIdx.x >> 5) * NBLK + blockIdx.x;
    for (int task = task0; task < 2048; task += NWARP) {
        int ks = task >> 9;
        int r0 = (task & 511) * 4;
        int s4 = ks * KC4, e4 = s4 + KC4;
        float a0 = 0.f, a1 = 0.f, a2 = 0.f, a3 = 0.f;

        int xe4 = (e4 < XLEN4) ? e4 : XLEN4;
        if (s4 < xe4) {
            const float4* xp = (const float4*)Xi + (size_t)s4 * 32 + lane;
            const float4* wp = (const float4*)Wih + (size_t)r0 * XLEN4 + s4;
            #pragma unroll 4
            for (int k4 = s4; k4 < xe4; k4++) {
                float4 x = *xp; xp += 32;
                float4 q0 = wp[0];
                float4 q1 = wp[XLEN4];
                float4 q2 = wp[2 * XLEN4];
                float4 q3 = wp[3 * XLEN4];
                wp++;
                a0 = fmaf(q0.x, x.x, a0); a0 = fmaf(q0.y, x.y, a0); a0 = fmaf(q0.z, x.z, a0); a0 = fmaf(q0.w, x.w, a0);
                a1 = fmaf(q1.x, x.x, a1); a1 = fmaf(q1.y, x.y, a1); a1 = fmaf(q1.z, x.z, a1); a1 = fmaf(q1.w, x.w, a1);
                a2 = fmaf(q2.x, x.x, a2); a2 = fmaf(q2.y, x.y, a2); a2 = fmaf(q2.z, x.z, a2); a2 = fmaf(q2.w, x.w, a2);
                a3 = fmaf(q3.x, x.x, a3); a3 = fmaf(q3.y, x.y, a3); a3 = fmaf(q3.z, x.z, a3); a3 = fmaf(q3.w, x.w, a3);
            }
        }
        int hs4 = (s4 > XLEN4) ? s4 : XLEN4;
        if (hs4 < e4) {
            const float4* hp = (const float4*)Hi + (size_t)(hs4 - XLEN4) * 32 + lane;
            const float4* vp = (const float4*)Whh + (size_t)r0 * 128 + (hs4 - XLEN4);
            #pragma unroll 4
            for (int k4 = hs4; k4 < e4; k4++) {
                float4 x = *hp; hp += 32;
                float4 q0 = vp[0];
                float4 q1 = vp[128];
                float4 q2 = vp[256];
                float4 q3 = vp[384];
                vp++;
                a0 = fmaf(q0.x, x.x, a0); a0 = fmaf(q0.y, x.y, a0); a0 = fmaf(q0.z, x.z, a0); a0 = fmaf(q0.w, x.w, a0);
                a1 = fmaf(q1.x, x.x, a1); a1 = fmaf(q1.y, x.y, a1); a1 = fmaf(q1.z, x.z, a1); a1 = fmaf(q1.w, x.w, a1);
                a2 = fmaf(q2.x, x.x, a2); a2 = fmaf(q2.y, x.y, a2); a2 = fmaf(q2.z, x.z, a2); a2 = fmaf(q2.w, x.w, a2);
                a3 = fmaf(q3.x, x.x, a3); a3 = fmaf(q3.y, x.y, a3); a3 = fmaf(q3.z, x.z, a3); a3 = fmaf(q3.w, x.w, a3);
            }
        }
        float* gp = g_gpart + ((size_t)ks * 2048 + r0) * 32 + lane;
        gp[0]  = a0;
        gp[32] = a1;
        gp[64] = a2;
        gp[96] = a3;
    }
}

// ---------------- LSTM cell phase: warp u = wid*NBLK + blockIdx.x, lane = b ----------------
__device__ __forceinline__ void cell_phase(const float* __restrict__ bih,
                                           const float* __restrict__ bhh,
                                           float* __restrict__ hi, float* __restrict__ c,
                                           int lane) {
    int u = (threadIdx.x >> 5) * NBLK + blockIdx.x;
    if (u < HH) {
        int b = lane;
        float g[4];
        #pragma unroll
        for (int gi = 0; gi < 4; gi++) {
            int row = gi * HH + u;
            float s = bih[row] + bhh[row];
            #pragma unroll
            for (int ks = 0; ks < 4; ks++)
                s += g_gpart[((size_t)ks * 2048 + row) * 32 + b];
            g[gi] = s;
        }
        float i_ = 1.f / (1.f + expf(-g[0]));
        float f_ = 1.f / (1.f + expf(-g[1]));
        float t_ = tanhf(g[2]);
        float o_ = 1.f / (1.f + expf(-g[3]));
        float cn = f_ * c[u * 32 + b] + i_ * t_;
        c[u * 32 + b] = cn;
        hi[XI(u, b)] = o_ * tanhf(cn);
    }
}

// ---------------- logits GEMM phase (split-K=4, 500 row-groups) ----------------
__device__ __forceinline__ void logits_phase(const float* __restrict__ Wc, int lane) {
    int task0 = (threadIdx.x >> 5) * NBLK + blockIdx.x;
    for (int task = task0; task < 2000; task += NWARP) {
        int ks = task / 500;
        int r0 = (task - ks * 500) * 4;
        const float* src = (ks < 2) ? g_h1i : g_ctxi;
        int koff = (ks & 1) * 64;
        const float4* xp = (const float4*)src + (size_t)koff * 32 + lane;
        const float4* wp = (const float4*)Wc + (size_t)r0 * 256 + ks * 64;
        float a0 = 0.f, a1 = 0.f, a2 = 0.f, a3 = 0.f;
        #pragma unroll 4
        for (int k4 = 0; k4 < 64; k4++) {
            float4 x = *xp; xp += 32;
            float4 q0 = wp[0];
            float4 q1 = wp[256];
            float4 q2 = wp[512];
            float4 q3 = wp[768];
            wp++;
            a0 = fmaf(q0.x, x.x, a0); a0 = fmaf(q0.y, x.y, a0); a0 = fmaf(q0.z, x.z, a0); a0 = fmaf(q0.w, x.w, a0);
            a1 = fmaf(q1.x, x.x, a1); a1 = fmaf(q1.y, x.y, a1); a1 = fmaf(q1.z, x.z, a1); a1 = fmaf(q1.w, x.w, a1);
            a2 = fmaf(q2.x, x.x, a2); a2 = fmaf(q2.y, x.y, a2); a2 = fmaf(q2.z, x.z, a2); a2 = fmaf(q2.w, x.w, a2);
            a3 = fmaf(q3.x, x.x, a3); a3 = fmaf(q3.y, x.y, a3); a3 = fmaf(q3.z, x.z, a3); a3 = fmaf(q3.w, x.w, a3);
        }
        float* lp = g_lpart + ((size_t)ks * VV + r0) * 32 + lane;
        lp[0]  = a0;
        lp[32] = a1;
        lp[64] = a2;
        lp[96] = a3;
    }
}

// ---------------- persistent megakernel: 100 decode steps, 7 grid barriers/step ----------------
__global__ __launch_bounds__(NTHR, 1)
void mega_kernel(const float* __restrict__ Lf,
                 const float* __restrict__ Wih0, const float* __restrict__ Whh0,
                 const float* __restrict__ bih0, const float* __restrict__ bhh0,
                 const float* __restrict__ Wih1, const float* __restrict__ Whh1,
                 const float* __restrict__ bih1, const float* __restrict__ bhh1,
                 const float* __restrict__ bphi,
                 const float* __restrict__ Wc,   const float* __restrict__ bc,
                 float* __restrict__ pred_out, float* __restrict__ attn_out) {
    __shared__ float h1s[512];
    __shared__ float cds[256];
    __shared__ float ats[256];
    __shared__ float red[16];

    const int tid = threadIdx.x;
    const int lane = tid & 31;
    const int b = blockIdx.x;   // batch id for attn/lsm phases (b < 32 active)

    for (int t = 0; t < NSTEP; t++) {
        // ---- LSTM layer 0 ----
        gemm_phase(Wih0, Whh0, g_X0, g_h0i, KX / 4, 189, lane);   // K=3024, 4 chunks of 756
        gsync();
        cell_phase(bih0, bhh0, g_h0i, g_c0, lane);
        gsync();
        // ---- LSTM layer 1 ----
        gemm_phase(Wih1, Whh1, g_h0i, g_h1i, HH / 4, 64, lane);   // K=1024, 4 chunks of 256
        gsync();
        cell_phase(bih1, bhh1, g_h1i, g_c1, lane);
        gsync();
        // ---- attention (blocks 0..31, one batch each) ----
        if (b < BB) {
            h1s[tid] = g_h1i[XI(tid, b)];
            __syncthreads();
            // phi: comp_dec[m] (threads 0..255)
            if (tid < MM) {
                float acc = bphi[tid];
                for (int d = 0; d < 512; d += 4) {
                    acc = fmaf(g_WphiT[(d + 0) * MM + tid], h1s[d + 0], acc);
                    acc = fmaf(g_WphiT[(d + 1) * MM + tid], h1s[d + 1], acc);
                    acc = fmaf(g_WphiT[(d + 2) * MM + tid], h1s[d + 2], acc);
                    acc = fmaf(g_WphiT[(d + 3) * MM + tid], h1s[d + 3], acc);
                }
                cds[tid] = fmaxf(acc, 0.f);
            }
            __syncthreads();
            // energy + softmax over t (threads 0..255 hold real values)
            float e = -INFINITY;
            if (tid < TT) {
                e = 0.f;
                const float* cl = &g_complis[b * MM * TT + tid];
                #pragma unroll 4
                for (int m = 0; m < MM; m++) e = fmaf(cds[m], cl[m * TT], e);
            }
            float mx = bmax512(e, red);
            float p = (tid < TT) ? expf(e - mx) : 0.f;
            float s = bsum512(p, red);
            if (tid < TT) {
                float a = p / s;
                ats[tid] = a;
                attn_out[(size_t)t * BB * TT + b * TT + tid] = a;
            }
            __syncthreads();
            // context: d = tid (512 dims)
            {
                int d = tid;
                float cv = 0.f;
                const float* lp = Lf + b * TT * DD + d;
                #pragma unroll 4
                for (int tt = 0; tt < TT; tt++) cv = fmaf(ats[tt], lp[tt * DD], cv);
                g_ctxi[XI(d, b)]    = cv;
                g_X0[XI(VV + d, b)] = cv;   // feedback: x_new[2000+d]
            }
        }
        gsync();
        // ---- logits GEMM ----
        logits_phase(Wc, lane);
        gsync();
        // ---- log_softmax + feedback (blocks 0..31) ----
        if (b < BB) {
            float l[4];
            float mx = -INFINITY;
            #pragma unroll
            for (int j = 0; j < 4; j++) {
                int v = tid + j * NTHR;
                if (v < VV) {
                    float s = bc[v];
                    #pragma unroll
                    for (int ks = 0; ks < 4; ks++)
                        s += g_lpart[((size_t)ks * VV + v) * 32 + b];
                    l[j] = s;
                } else l[j] = -INFINITY;
                mx = fmaxf(mx, l[j]);
            }
            mx = bmax512(mx, red);
            float s = 0.f;
            #pragma unroll
            for (int j = 0; j < 4; j++) s += expf(l[j] - mx);
            s = bsum512(s, red);
            float lg = logf(s) + mx;
            #pragma unroll
            for (int j = 0; j < 4; j++) {
                int v = tid + j * NTHR;
                if (v < VV) {
                    float lp = l[j] - lg;
                    pred_out[(size_t)t * BB * VV + b * VV + v] = lp;
                    g_X0[XI(v, b)] = lp;   // feedback: x_new[0..1999]
                }
            }
        }
        gsync();   // protects g_X0 / g_lpart / g_gpart for next step
    }
}

// ---------------- host ----------------
extern "C" void kernel_launch(void* const* d_in, const int* in_sizes, int n_in,
                              void* d_out, int out_size) {
    const float* Lf   = (const float*)d_in[0];
    const float* Wih0 = (const float*)d_in[1];
    const float* Whh0 = (const float*)d_in[2];
    const float* bih0 = (const float*)d_in[3];
    const float* bhh0 = (const float*)d_in[4];
    const float* Wih1 = (const float*)d_in[5];
    const float* Whh1 = (const float*)d_in[6];
    const float* bih1 = (const float*)d_in[7];
    const float* bhh1 = (const float*)d_in[8];
    const float* Wphi = (const float*)d_in[9];
    const float* bphi = (const float*)d_in[10];
    const float* Wpsi = (const float*)d_in[11];
    const float* bpsi = (const float*)d_in[12];
    const float* Wc   = (const float*)d_in[13];
    const float* bc   = (const float*)d_in[14];

    float* out = (float*)d_out;
    float* pred_out = out;                                  // [100][32][2000]
    float* attn_out = out + (size_t)NSTEP * BB * VV;        // [100][32][256]

    const int initN = KX * BB + 4 * HH * BB + HH * MM + DD * MM;
    init_kernel<<<(initN + 255) / 256, 256>>>(Lf, Wphi, Wpsi);
    psi_kernel<<<512, 256>>>(Lf, bpsi);
    mega_kernel<<<NBLK, NTHR>>>(Lf, Wih0, Whh0, bih0, bhh0,
                                Wih1, Whh1, bih1, bhh1,
                                bphi, Wc, bc, pred_out, attn_out);
}